// round 13
// baseline (speedup 1.0000x reference)
#include <cuda_runtime.h>
#include <math.h>

#define BMAX 65536
#define CH 12
#define LRAW 63
#define FLEN 7
#define VLEN 57
#define FIN 168
#define FGH 35
#define EN1 16
#define EN2 32
#define KW 6
#define L1 18
#define L2 5
#define Y1N (EN1 * L1)   // 288
#define Y2N (EN2 * L2)   // 160
#define DEH 10
#define DEOUT 50

// global scratch (allocation-free: __device__ globals)
__device__ float g_filt[(size_t)FLEN * BMAX];         // transposed [k][B]
__device__ float2 g_y1p[(size_t)(BMAX / 2) * Y1N];
__device__ float2 g_y2p[(size_t)(BMAX / 2) * Y2N];
__device__ float g_stats[96];

// ---------------- packed fp32x2 helpers (sm_103a FFMA2 path) ----------------
__device__ __forceinline__ float2 f2fma(float2 a, float2 b, float2 c) {
    unsigned long long ua = reinterpret_cast<unsigned long long&>(a);
    unsigned long long ub = reinterpret_cast<unsigned long long&>(b);
    unsigned long long uc = reinterpret_cast<unsigned long long&>(c);
    unsigned long long ud;
    asm("fma.rn.f32x2 %0, %1, %2, %3;" : "=l"(ud) : "l"(ua), "l"(ub), "l"(uc));
    return reinterpret_cast<float2&>(ud);
}
__device__ __forceinline__ float2 f2mul(float2 a, float2 b) {
    unsigned long long ua = reinterpret_cast<unsigned long long&>(a);
    unsigned long long ub = reinterpret_cast<unsigned long long&>(b);
    unsigned long long ud;
    asm("mul.rn.f32x2 %0, %1, %2;" : "=l"(ud) : "l"(ua), "l"(ub));
    return reinterpret_cast<float2&>(ud);
}
__device__ __forceinline__ float2 f2add(float2 a, float2 b) {
    unsigned long long ua = reinterpret_cast<unsigned long long&>(a);
    unsigned long long ub = reinterpret_cast<unsigned long long&>(b);
    unsigned long long ud;
    asm("add.rn.f32x2 %0, %1, %2;" : "=l"(ud) : "l"(ua), "l"(ub));
    return reinterpret_cast<float2&>(ud);
}
__device__ __forceinline__ float2 fdup(float x) { return make_float2(x, x); }
__device__ __forceinline__ float2 lo2(float4 q) { return make_float2(q.x, q.y); }
__device__ __forceinline__ float2 hi2(float4 q) { return make_float2(q.z, q.w); }

// precise tanh: (e^{2x}-1)/(e^{2x}+1), rel err ~1e-6 (output-facing paths)
__device__ __forceinline__ float ftanh(float x) {
    float xc = fminf(fmaxf(x, -9.0f), 9.0f);
    float t  = __expf(xc + xc);
    return __fdividef(t - 1.0f, t + 1.0f);
}
__device__ __forceinline__ float2 ftanh2(float2 v) {
    return make_float2(ftanh(v.x), ftanh(v.y));
}
// HW tanh (sm_75+ MUFU.TANH), max rel err ~2^-11 — internal layers only
__device__ __forceinline__ float ftanha(float x) {
    float y;
    asm("tanh.approx.f32 %0, %1;" : "=f"(y) : "f"(x));
    return y;
}
__device__ __forceinline__ float2 ftanha2(float2 v) {
    return make_float2(ftanha(v.x), ftanha(v.y));
}

// ================= K1a: filter generator, 4 samples per warp ================
#define K1A_WARPS 16
#define K1A_BASE 6172
#define K1A_WREG 944
#define K1A_SMEMF (K1A_BASE + K1A_WARPS * K1A_WREG)

__global__ void __launch_bounds__(K1A_WARPS * 32) k1a_kernel(
    const float* __restrict__ eegf,
    const float* __restrict__ fg_w1, const float* __restrict__ fg_b1,
    const float* __restrict__ fg_w2, const float* __restrict__ fg_b2,
    int bsz)
{
    extern __shared__ float sm[];
    float* s_w1T = sm;
    float* s_b1  = sm + 5880;
    float* s_w2  = sm + 5916;
    float* s_b2  = sm + 6164;

    const int tid = threadIdx.x;
    if (blockIdx.x == 0 && tid < 96) g_stats[tid] = 0.0f;
    for (int idx = tid; idx < FGH * FIN; idx += blockDim.x) {
        int j = idx / FIN, i = idx - j * FIN;
        s_w1T[i * FGH + j] = fg_w1[idx];
    }
    if (tid < FGH)  s_b1[tid] = fg_b1[tid];
    for (int idx = tid; idx < FLEN * FGH; idx += blockDim.x) s_w2[idx] = fg_w2[idx];
    if (tid < FLEN) s_b2[tid] = fg_b2[tid];
    __syncthreads();

    const int lane = tid & 31;
    const int wpb  = blockDim.x >> 5;
    const int gw   = blockIdx.x * wpb + (tid >> 5);
    const int nw   = gridDim.x * wpb;

    float* wbase = sm + K1A_BASE + (tid >> 5) * K1A_WREG;
    float2* sXA  = (float2*)wbase;
    float2* sXB  = (float2*)(wbase + 336);
    float2* sH1A = (float2*)(wbase + 672);
    float2* sH1B = (float2*)(wbase + 744);
    float2* sP2A = (float2*)(wbase + 816);
    float2* sP2B = (float2*)(wbase + 876);

    const int npairs = bsz >> 1;
    const int nquads = (npairs + 1) >> 1;

    for (int q = gw; q < nquads; q += nw) {
        const int pA = 2 * q;
        const int pB = (2 * q + 1 < npairs) ? 2 * q + 1 : 2 * q;
        const int bA = 2 * pA, bB = 2 * pB;

        const float* efA0 = eegf + (size_t)bA * FIN;
        const float* efA1 = efA0 + FIN;
        const float* efB0 = eegf + (size_t)bB * FIN;
        const float* efB1 = efB0 + FIN;
        for (int i = lane; i < FIN; i += 32) {
            sXA[i] = make_float2(efA0[i], efA1[i]);
            sXB[i] = make_float2(efB0[i], efB1[i]);
        }
        __syncwarp();

        float2 aA = fdup(s_b1[lane]);
        float2 aB = aA;
        #pragma unroll 4
        for (int i = 0; i < FIN; i++) {
            float2 wv = fdup(s_w1T[i * FGH + lane]);
            aA = f2fma(sXA[i], wv, aA);
            aB = f2fma(sXB[i], wv, aB);
        }
        if (lane < 30) {
            int j = 32 + lane / 10;
            float2 pA2 = make_float2(0.f, 0.f), pB2 = make_float2(0.f, 0.f);
            for (int i = lane % 10; i < FIN; i += 10) {
                float2 wv = fdup(s_w1T[i * FGH + j]);
                pA2 = f2fma(sXA[i], wv, pA2);
                pB2 = f2fma(sXB[i], wv, pB2);
            }
            sP2A[lane] = pA2; sP2B[lane] = pB2;
        }
        sH1A[lane] = ftanha2(aA);
        sH1B[lane] = ftanha2(aB);
        __syncwarp();
        if (lane < 3) {
            float2 tA = fdup(s_b1[32 + lane]);
            float2 tB = tA;
            #pragma unroll
            for (int s = 0; s < 10; s++) {
                tA = f2add(tA, sP2A[lane * 10 + s]);
                tB = f2add(tB, sP2B[lane * 10 + s]);
            }
            sH1A[32 + lane] = ftanha2(tA);
            sH1B[32 + lane] = ftanha2(tB);
        }
        __syncwarp();

        if (lane < FLEN) {
            float2 cA = fdup(s_b2[lane]);
            float2 cB = cA;
            #pragma unroll
            for (int i = 0; i < FGH; i++) {
                float2 wv = fdup(s_w2[lane * FGH + i]);
                cA = f2fma(sH1A[i], wv, cA);
                cB = f2fma(sH1B[i], wv, cB);
            }
            float* gf = g_filt + (size_t)lane * bsz;
            *(float2*)(gf + bA) = ftanh2(cA);   // precise: multiplicative path
            *(float2*)(gf + bB) = ftanh2(cB);
        }
        __syncwarp();
    }
}

// ============ K1b: adaptive filter + conv1 (LDS.128 streamed windows) =======
// rolling window (R11) + forced 4 blocks/SM (64-reg target, smem 55KB -> 220KB)
#define K1B_WARPS 8
#define K1B_BASE 2512
#define K1B_WREG 1404
#define K1B_SMEMF (K1B_BASE + K1B_WARPS * K1B_WREG)

__global__ void __launch_bounds__(K1B_WARPS * 32, 4) k1b_kernel(
    const float* __restrict__ raw,
    const float* __restrict__ enc_w1, const float* __restrict__ enc_b1,
    int bsz)
{
    extern __shared__ float sm[];
    float2* s_cw2 = (float2*)sm;          // [o*78 + c*6 + k] duplicated f2
    float*  s_cb  = sm + 2496;

    const int tid = threadIdx.x;
    for (int idx = tid; idx < EN1 * CH * KW; idx += blockDim.x) {
        int o = idx / (CH * KW), r = idx - o * (CH * KW);
        float w = enc_w1[idx];
        s_cw2[o * 78 + r] = make_float2(w, w);
    }
    if (tid < EN1) s_cb[tid] = enc_b1[tid];
    __syncthreads();

    const int lane = tid & 31;
    const int wpb  = blockDim.x >> 5;
    const int gw   = blockIdx.x * wpb + (tid >> 5);
    const int nw   = gridDim.x * wpb;

    float2* sEegP = (float2*)(sm + K1B_BASE + (tid >> 5) * K1B_WREG);

    float bnS = 0.0f, bnQ = 0.0f;
    const int o   = lane >> 1;          // conv1 out channel
    const int hb  = lane & 1;           // t-half: 0 -> t 0..9, 1 -> t 10..17
    const int tb  = hb * 10;
    const int ns  = 10 - 2 * hb;        // valid outputs this half
    const int cl0 = lane >> 3;          // eeg: channel-part 0..3
    const int seg = lane & 7;           // eeg: 8-t segment
    const int t0  = seg * 8;
    const int nt  = (t0 + 8 <= VLEN) ? 8 : (VLEN - t0);
    const int npairs = bsz >> 1;

    for (int p = gw; p < npairs; p += nw) {
        const int b0 = 2 * p;

        const float* gf = g_filt;
        const float2 f0 = *(const float2*)(gf + 0 * (size_t)bsz + b0);
        const float2 f1 = *(const float2*)(gf + 1 * (size_t)bsz + b0);
        const float2 f2v= *(const float2*)(gf + 2 * (size_t)bsz + b0);
        const float2 f3 = *(const float2*)(gf + 3 * (size_t)bsz + b0);
        const float2 f4 = *(const float2*)(gf + 4 * (size_t)bsz + b0);
        const float2 f5 = *(const float2*)(gf + 5 * (size_t)bsz + b0);
        const float2 f6 = *(const float2*)(gf + 6 * (size_t)bsz + b0);

        // ---- adaptive filter: register sliding window, direct LDG ----
        const float* rb0 = raw + (size_t)b0 * (CH * LRAW);
        #pragma unroll
        for (int ch = 0; ch < 3; ch++) {
            const int c = ch * 4 + cl0;
            const float* r0 = rb0 + c * LRAW + t0;
            const float* r1 = r0 + CH * LRAW;
            float2 w0 = make_float2(r0[0], r1[0]);
            float2 w1 = make_float2(r0[1], r1[1]);
            float2 w2 = make_float2(r0[2], r1[2]);
            float2 w3 = make_float2(r0[3], r1[3]);
            float2 w4 = make_float2(r0[4], r1[4]);
            float2 w5 = make_float2(r0[5], r1[5]);
            float2 w6 = make_float2(r0[6], r1[6]);
            float2* eout = sEegP + c * 58 + t0;
            #pragma unroll
            for (int t = 0; t < 8; t++) {
                if (t < nt) {
                    float2 a = f2mul(w0, f0);
                    a = f2fma(w1, f1, a);  a = f2fma(w2, f2v, a);
                    a = f2fma(w3, f3, a);  a = f2fma(w4, f4, a);
                    a = f2fma(w5, f5, a);  a = f2fma(w6, f6, a);
                    eout[t] = a;
                    if (t < 7) {
                        w0 = w1; w1 = w2; w2 = w3; w3 = w4; w4 = w5; w5 = w6;
                        w6 = make_float2(r0[t + 7], r1[t + 7]);
                    }
                }
            }
        }
        __syncwarp();

        // ---- conv1: 10 windows/lane, eeg streamed via LDS.128 chunks ----
        float2 accc[10];
        {
            float2 cb2 = fdup(s_cb[o]);
            #pragma unroll
            for (int i = 0; i < 10; i++) accc[i] = cb2;
        }
        #pragma unroll
        for (int c = 0; c < CH; c++) {
            const float4* wq = (const float4*)(s_cw2 + o * 78 + c * 6);
            const float4 wA = wq[0], wB = wq[1], wC = wq[2];
            const float2 W0 = lo2(wA), W1 = hi2(wA), W2 = lo2(wB),
                         W3 = hi2(wB), W4 = lo2(wC), W5 = hi2(wC);
            const float4* e4 = (const float4*)(sEegP + c * 58 + hb * 30);

            #define CONV_STEP(i, E0, E1, E2, E3, E4, E5)                     \
                { float2 a = accc[i];                                        \
                  a = f2fma(E0, W0, a); a = f2fma(E1, W1, a);                \
                  a = f2fma(E2, W2, a); a = f2fma(E3, W3, a);                \
                  a = f2fma(E4, W4, a); a = f2fma(E5, W5, a);                \
                  accc[i] = a; }

            float4 qa = e4[0], qb = e4[1], qc = e4[2];
            CONV_STEP(0, lo2(qa), hi2(qa), lo2(qb), hi2(qb), lo2(qc), hi2(qc))
            float4 qd = e4[3], qe = e4[4];
            CONV_STEP(1, hi2(qb), lo2(qc), hi2(qc), lo2(qd), hi2(qd), lo2(qe))
            float4 qf = e4[5];
            CONV_STEP(2, lo2(qd), hi2(qd), lo2(qe), hi2(qe), lo2(qf), hi2(qf))
            float4 qg = e4[6], qh = e4[7];
            CONV_STEP(3, hi2(qe), lo2(qf), hi2(qf), lo2(qg), hi2(qg), lo2(qh))
            float4 qi = e4[8];
            CONV_STEP(4, lo2(qg), hi2(qg), lo2(qh), hi2(qh), lo2(qi), hi2(qi))
            float4 qj = e4[9], qk = e4[10];
            CONV_STEP(5, hi2(qh), lo2(qi), hi2(qi), lo2(qj), hi2(qj), lo2(qk))
            float4 ql = e4[11];
            CONV_STEP(6, lo2(qj), hi2(qj), lo2(qk), hi2(qk), lo2(ql), hi2(ql))
            float4 qm = e4[12], qn = e4[13];
            CONV_STEP(7, hi2(qk), lo2(ql), hi2(ql), lo2(qm), hi2(qm), lo2(qn))
            float4 qo = e4[14];
            CONV_STEP(8, lo2(qm), hi2(qm), lo2(qn), hi2(qn), lo2(qo), hi2(qo))
            float4 qp = e4[15], qq = e4[16];
            CONV_STEP(9, hi2(qn), lo2(qo), hi2(qo), lo2(qp), hi2(qp), lo2(qq))
            #undef CONV_STEP
        }

        float2* gy = g_y1p + (size_t)p * Y1N;
        #pragma unroll
        for (int i = 0; i < 10; i++) {
            if (i < ns) {
                float2 v = accc[i];
                gy[o * L1 + tb + i] = v;
                bnS += v.x + v.y;
                bnQ = fmaf(v.x, v.x, fmaf(v.y, v.y, bnQ));
            }
        }
        __syncwarp();
    }
    bnS += __shfl_down_sync(0xffffffffu, bnS, 1);
    bnQ += __shfl_down_sync(0xffffffffu, bnQ, 1);
    if ((lane & 1) == 0) {
        atomicAdd(&g_stats[o], bnS);
        atomicAdd(&g_stats[EN1 + o], bnQ);
    }
}

// -------- K2: BN1+tanh (float4), conv2 over two pairs, BN2 partials ---------
#define K2_WARPS 8
#define K2_SMEMF (3200 + K2_WARPS * 1152)

__global__ void __launch_bounds__(K2_WARPS * 32, 3) k2_kernel(
    const float* __restrict__ enc_w2, const float* __restrict__ enc_b2,
    const float* __restrict__ bn1_g, const float* __restrict__ bn1_b,
    int bsz)
{
    extern __shared__ float sm[];
    float*  s_w   = sm;                      // scalar [r*32 + o]
    float2* s_bd  = (float2*)(sm + 3072);
    float2* s_scP = (float2*)(sm + 3136);
    float2* s_shP = (float2*)(sm + 3168);

    const int tid = threadIdx.x;
    for (int idx = tid; idx < EN2 * EN1 * KW; idx += blockDim.x) {
        int o = idx / (EN1 * KW), r = idx - o * (EN1 * KW);
        s_w[r * 32 + o] = enc_w2[idx];
    }
    if (tid < EN2) s_bd[tid] = fdup(enc_b2[tid]);
    if (tid < EN1) {
        float inv = 1.0f / ((float)bsz * (float)L1);
        float m = g_stats[tid] * inv;
        float v = g_stats[EN1 + tid] * inv - m * m;
        float r = rsqrtf(v + 1e-5f);
        float sc = bn1_g[tid] * r;
        s_scP[tid] = fdup(sc);
        s_shP[tid] = fdup(bn1_b[tid] - m * sc);
    }
    __syncthreads();

    const int lane = tid & 31;
    const int w    = tid >> 5;
    const int wpb  = blockDim.x >> 5;
    const int gw   = blockIdx.x * wpb + w;
    const int nw   = gridDim.x * wpb;
    float2* sHP0 = (float2*)(sm + 3200) + w * 576;
    float2* sHP1 = sHP0 + 288;

    float bnS = 0.f, bnQ = 0.f;
    const int o = lane;
    const int npairs = bsz >> 1;
    const int nquads = npairs >> 1;

    for (int q = gw; q < nquads; q += nw) {
        const int p0 = 2 * q, p1 = 2 * q + 1;
        const float4* gy0 = (const float4*)(g_y1p + (size_t)p0 * Y1N);
        const float4* gy1 = (const float4*)(g_y1p + (size_t)p1 * Y1N);
        float4* d0 = (float4*)sHP0;
        float4* d1 = (float4*)sHP1;
        #pragma unroll
        for (int j = 0; j < 5; j++) {
            int idx4 = lane + 32 * j;
            if (idx4 < 144) {
                unsigned c = (unsigned)idx4 / 9u;
                float2 sc = s_scP[c], sh = s_shP[c];
                float4 q0 = gy0[idx4], q1 = gy1[idx4];
                float2 a0 = ftanha2(f2fma(make_float2(q0.x, q0.y), sc, sh));
                float2 a1 = ftanha2(f2fma(make_float2(q0.z, q0.w), sc, sh));
                float2 b0 = ftanha2(f2fma(make_float2(q1.x, q1.y), sc, sh));
                float2 b1 = ftanha2(f2fma(make_float2(q1.z, q1.w), sc, sh));
                d0[idx4] = make_float4(a0.x, a0.y, a1.x, a1.y);
                d1[idx4] = make_float4(b0.x, b0.y, b1.x, b1.y);
            }
        }
        __syncwarp();

        float2 acc0[L2], acc1[L2];
        {
            float2 b2 = s_bd[o];
            #pragma unroll
            for (int t = 0; t < L2; t++) { acc0[t] = b2; acc1[t] = b2; }
        }
        #pragma unroll
        for (int c = 0; c < EN1; c++) {
            const float* wp = s_w + (c * KW) * 32 + o;
            float2 W[KW];
            #pragma unroll
            for (int k = 0; k < KW; k++) W[k] = fdup(wp[k * 32]);

            const float4* h40 = reinterpret_cast<const float4*>(sHP0 + c * L1);
            const float4* h41 = reinterpret_cast<const float4*>(sHP1 + c * L1);
            float2 g0[L1], g1[L1];
            #pragma unroll
            for (int x = 0; x < 9; x++) {
                float4 q0 = h40[x], q1 = h41[x];
                g0[2 * x]     = make_float2(q0.x, q0.y);
                g0[2 * x + 1] = make_float2(q0.z, q0.w);
                g1[2 * x]     = make_float2(q1.x, q1.y);
                g1[2 * x + 1] = make_float2(q1.z, q1.w);
            }
            #pragma unroll
            for (int k = 0; k < KW; k++) {
                #pragma unroll
                for (int t = 0; t < L2; t++) {
                    acc0[t] = f2fma(g0[3 * t + k], W[k], acc0[t]);
                    acc1[t] = f2fma(g1[3 * t + k], W[k], acc1[t]);
                }
            }
        }
        float2* g20 = g_y2p + (size_t)p0 * Y2N;
        float2* g21 = g_y2p + (size_t)p1 * Y2N;
        #pragma unroll
        for (int t = 0; t < L2; t++) {
            g20[o * L2 + t] = acc0[t];
            g21[o * L2 + t] = acc1[t];
            bnS += acc0[t].x + acc0[t].y + acc1[t].x + acc1[t].y;
            bnQ = fmaf(acc0[t].x, acc0[t].x, fmaf(acc0[t].y, acc0[t].y, bnQ));
            bnQ = fmaf(acc1[t].x, acc1[t].x, fmaf(acc1[t].y, acc1[t].y, bnQ));
        }
        __syncwarp();
    }
    atomicAdd(&g_stats[32 + o], bnS);
    atomicAdd(&g_stats[64 + o], bnQ);
}

// ---- K3: BN2+tanh, heads, reparam, decoder — loop-invariants in registers --
#define K3_WPB 8
__global__ void __launch_bounds__(K3_WPB * 32) k3_kernel(
    const float* __restrict__ eps,
    const float* __restrict__ mu_w, const float* __restrict__ mu_b,
    const float* __restrict__ lv_w, const float* __restrict__ lv_b,
    const float* __restrict__ de_w1, const float* __restrict__ de_b1,
    const float* __restrict__ de_w2, const float* __restrict__ de_b2,
    const float* __restrict__ bn2_g, const float* __restrict__ bn2_b,
    float* __restrict__ out, int bsz)
{
    __shared__ float  s_dw1[DEH * 2], s_db1[DEH];
    __shared__ float2 s_dw2d[DEOUT * DEH];
    __shared__ float2 s_db2d[DEOUT];
    __shared__ float  s_sc[EN2], s_sh[EN2];
    __shared__ float2 s_d[K3_WPB][12];

    const int tid = threadIdx.x;
    for (int i = tid; i < DEH * 2; i += blockDim.x) s_dw1[i] = de_w1[i];
    if (tid < DEH) s_db1[tid] = de_b1[tid];
    for (int i = tid; i < DEOUT * DEH; i += blockDim.x) s_dw2d[i] = fdup(de_w2[i]);
    if (tid < DEOUT) s_db2d[tid] = fdup(de_b2[tid]);
    if (tid < EN2) {
        float inv = 1.0f / ((float)bsz * (float)L2);
        float m = g_stats[32 + tid] * inv;
        float v = g_stats[64 + tid] * inv - m * m;
        float r = rsqrtf(v + 1e-5f);
        float sc = bn2_g[tid] * r;
        s_sc[tid] = sc;
        s_sh[tid] = bn2_b[tid] - m * sc;
    }
    __syncthreads();

    const int lane = tid & 31;
    const int w    = tid >> 5;

    float2 rmu0[5], rmu1[5], rlv0[5], rlv1[5], rsc[5], rsh[5];
    #pragma unroll
    for (int j = 0; j < 5; j++) {
        int i = lane + 32 * j;
        int c = i / L2;
        rmu0[j] = fdup(mu_w[i]);       rmu1[j] = fdup(mu_w[Y2N + i]);
        rlv0[j] = fdup(lv_w[i]);       rlv1[j] = fdup(lv_w[Y2N + i]);
        rsc[j]  = fdup(s_sc[c]);       rsh[j]  = fdup(s_sh[c]);
    }
    const float mub0 = mu_b[0], mub1 = mu_b[1];
    const float lvb0 = lv_b[0], lvb1 = lv_b[1];

    const int wpb  = blockDim.x >> 5;
    const int gw   = blockIdx.x * wpb + w;
    const int nw   = gridDim.x * wpb;
    const int npairs = bsz >> 1;

    float* outO = out;
    float* outM = out + (size_t)bsz * DEOUT;
    float* outV = out + (size_t)bsz * (DEOUT + 2);

    for (int p = gw; p < npairs; p += nw) {
        const int b0 = 2 * p;
        const float2* gy = g_y2p + (size_t)p * Y2N;
        float2 pm0 = make_float2(0.f, 0.f), pm1 = pm0, pl0 = pm0, pl1 = pm0;
        #pragma unroll
        for (int j = 0; j < 5; j++) {
            float2 v = ftanha2(f2fma(gy[lane + 32 * j], rsc[j], rsh[j]));
            pm0 = f2fma(v, rmu0[j], pm0);
            pm1 = f2fma(v, rmu1[j], pm1);
            pl0 = f2fma(v, rlv0[j], pl0);
            pl1 = f2fma(v, rlv1[j], pl1);
        }
        #pragma unroll
        for (int off = 16; off > 0; off >>= 1) {
            pm0.x += __shfl_xor_sync(0xffffffffu, pm0.x, off);
            pm0.y += __shfl_xor_sync(0xffffffffu, pm0.y, off);
            pm1.x += __shfl_xor_sync(0xffffffffu, pm1.x, off);
            pm1.y += __shfl_xor_sync(0xffffffffu, pm1.y, off);
            pl0.x += __shfl_xor_sync(0xffffffffu, pl0.x, off);
            pl0.y += __shfl_xor_sync(0xffffffffu, pl0.y, off);
            pl1.x += __shfl_xor_sync(0xffffffffu, pl1.x, off);
            pl1.y += __shfl_xor_sync(0xffffffffu, pl1.y, off);
        }
        float2 mu0 = f2add(pm0, fdup(mub0));
        float2 mu1 = f2add(pm1, fdup(mub1));
        float2 lv0 = f2add(pl0, fdup(lvb0));
        float2 lv1 = f2add(pl1, fdup(lvb1));
        const float4 ev = *(const float4*)(eps + (size_t)b0 * 2);
        float2 z0 = make_float2(fmaf(ev.x, __expf(0.5f * lv0.x), mu0.x),
                                fmaf(ev.z, __expf(0.5f * lv0.y), mu0.y));
        float2 z1 = make_float2(fmaf(ev.y, __expf(0.5f * lv1.x), mu1.x),
                                fmaf(ev.w, __expf(0.5f * lv1.y), mu1.y));

        if (lane < DEH) {
            float2 a = f2fma(z0, fdup(s_dw1[lane * 2]),
                       f2fma(z1, fdup(s_dw1[lane * 2 + 1]), fdup(s_db1[lane])));
            s_d[w][lane] = ftanha2(a);
        }
        __syncwarp();
        float2 dreg[DEH];
        #pragma unroll
        for (int j = 0; j < DEH; j++) dreg[j] = s_d[w][j];

        float* oo0 = outO + (size_t)b0 * DEOUT;
        float* oo1 = oo0 + DEOUT;
        for (int k = lane; k < DEOUT; k += 32) {
            float2 a = s_db2d[k];
            #pragma unroll
            for (int j = 0; j < DEH; j++)
                a = f2fma(dreg[j], s_dw2d[k * DEH + j], a);
            a = ftanh2(a);   // precise: final output
            oo0[k] = a.x;
            oo1[k] = a.y;
        }
        if (lane == 0) {
            *(float2*)(outM + (size_t)b0 * 2)       = make_float2(mu0.x, mu1.x);
            *(float2*)(outM + (size_t)(b0 + 1) * 2) = make_float2(mu0.y, mu1.y);
            *(float2*)(outV + (size_t)b0 * 2)       = make_float2(lv0.x, lv1.x);
            *(float2*)(outV + (size_t)(b0 + 1) * 2) = make_float2(lv0.y, lv1.y);
        }
        __syncwarp();
    }
}

extern "C" void kernel_launch(void* const* d_in, const int* in_sizes, int n_in,
                              void* d_out, int out_size)
{
    const float* raw    = (const float*)d_in[0];
    const float* eegf   = (const float*)d_in[1];
    const float* eps    = (const float*)d_in[2];
    const float* fg_w1  = (const float*)d_in[3];
    const float* fg_b1  = (const float*)d_in[4];
    const float* fg_w2  = (const float*)d_in[5];
    const float* fg_b2  = (const float*)d_in[6];
    const float* enc_w1 = (const float*)d_in[7];
    const float* enc_b1 = (const float*)d_in[8];
    const float* bn1_g  = (const float*)d_in[9];
    const float* bn1_b  = (const float*)d_in[10];
    const float* enc_w2 = (const float*)d_in[11];
    const float* enc_b2 = (const float*)d_in[12];
    const float* bn2_g  = (const float*)d_in[13];
    const float* bn2_b  = (const float*)d_in[14];
    const float* mu_w   = (const float*)d_in[15];
    const float* mu_b   = (const float*)d_in[16];
    const float* lv_w   = (const float*)d_in[17];
    const float* lv_b   = (const float*)d_in[18];
    const float* de_w1  = (const float*)d_in[19];
    const float* de_b1  = (const float*)d_in[20];
    const float* de_w2  = (const float*)d_in[21];
    const float* de_b2  = (const float*)d_in[22];

    int bsz = in_sizes[0] / (CH * LRAW);

    size_t smemA = (size_t)K1A_SMEMF * sizeof(float);
    cudaFuncSetAttribute((const void*)k1a_kernel,
                         cudaFuncAttributeMaxDynamicSharedMemorySize, (int)smemA);
    k1a_kernel<<<296, K1A_WARPS * 32, smemA>>>(eegf, fg_w1, fg_b1, fg_w2, fg_b2, bsz);

    size_t smemB = (size_t)K1B_SMEMF * sizeof(float);
    cudaFuncSetAttribute((const void*)k1b_kernel,
                         cudaFuncAttributeMaxDynamicSharedMemorySize, (int)smemB);
    k1b_kernel<<<592, K1B_WARPS * 32, smemB>>>(raw, enc_w1, enc_b1, bsz);

    size_t smem2 = (size_t)K2_SMEMF * sizeof(float);
    cudaFuncSetAttribute((const void*)k2_kernel,
                         cudaFuncAttributeMaxDynamicSharedMemorySize, (int)smem2);
    k2_kernel<<<444, K2_WARPS * 32, smem2>>>(enc_w2, enc_b2, bn1_g, bn1_b, bsz);

    k3_kernel<<<444, K3_WPB * 32>>>(eps, mu_w, mu_b, lv_w, lv_b,
                                    de_w1, de_b1, de_w2, de_b2,
                                    bn2_g, bn2_b, (float*)d_out, bsz);
}

// round 14
// speedup vs baseline: 1.0289x; 1.0289x over previous
#include <cuda_runtime.h>
#include <math.h>

#define BMAX 65536
#define CH 12
#define LRAW 63
#define FLEN 7
#define VLEN 57
#define FIN 168
#define FGH 35
#define EN1 16
#define EN2 32
#define KW 6
#define L1 18
#define L2 5
#define Y1N (EN1 * L1)   // 288
#define Y2N (EN2 * L2)   // 160
#define DEH 10
#define DEOUT 50

// global scratch (allocation-free: __device__ globals)
__device__ float g_filt[(size_t)FLEN * BMAX];         // transposed [k][B]
__device__ float2 g_y1p[(size_t)(BMAX / 2) * Y1N];
__device__ float2 g_y2p[(size_t)(BMAX / 2) * Y2N];
__device__ float g_stats[96];

// ---------------- packed fp32x2 helpers (sm_103a FFMA2 path) ----------------
__device__ __forceinline__ float2 f2fma(float2 a, float2 b, float2 c) {
    unsigned long long ua = reinterpret_cast<unsigned long long&>(a);
    unsigned long long ub = reinterpret_cast<unsigned long long&>(b);
    unsigned long long uc = reinterpret_cast<unsigned long long&>(c);
    unsigned long long ud;
    asm("fma.rn.f32x2 %0, %1, %2, %3;" : "=l"(ud) : "l"(ua), "l"(ub), "l"(uc));
    return reinterpret_cast<float2&>(ud);
}
__device__ __forceinline__ float2 f2mul(float2 a, float2 b) {
    unsigned long long ua = reinterpret_cast<unsigned long long&>(a);
    unsigned long long ub = reinterpret_cast<unsigned long long&>(b);
    unsigned long long ud;
    asm("mul.rn.f32x2 %0, %1, %2;" : "=l"(ud) : "l"(ua), "l"(ub));
    return reinterpret_cast<float2&>(ud);
}
__device__ __forceinline__ float2 f2add(float2 a, float2 b) {
    unsigned long long ua = reinterpret_cast<unsigned long long&>(a);
    unsigned long long ub = reinterpret_cast<unsigned long long&>(b);
    unsigned long long ud;
    asm("add.rn.f32x2 %0, %1, %2;" : "=l"(ud) : "l"(ua), "l"(ub));
    return reinterpret_cast<float2&>(ud);
}
__device__ __forceinline__ float2 fdup(float x) { return make_float2(x, x); }
__device__ __forceinline__ float2 lo2(float4 q) { return make_float2(q.x, q.y); }
__device__ __forceinline__ float2 hi2(float4 q) { return make_float2(q.z, q.w); }

// precise tanh: (e^{2x}-1)/(e^{2x}+1), rel err ~1e-6 (output-facing paths)
__device__ __forceinline__ float ftanh(float x) {
    float xc = fminf(fmaxf(x, -9.0f), 9.0f);
    float t  = __expf(xc + xc);
    return __fdividef(t - 1.0f, t + 1.0f);
}
__device__ __forceinline__ float2 ftanh2(float2 v) {
    return make_float2(ftanh(v.x), ftanh(v.y));
}
// HW tanh (sm_75+ MUFU.TANH), max rel err ~2^-11 — internal layers only
__device__ __forceinline__ float ftanha(float x) {
    float y;
    asm("tanh.approx.f32 %0, %1;" : "=f"(y) : "f"(x));
    return y;
}
__device__ __forceinline__ float2 ftanha2(float2 v) {
    return make_float2(ftanha(v.x), ftanha(v.y));
}

// ================= K1a: filter generator, 4 samples per warp ================
#define K1A_WARPS 16
#define K1A_BASE 6172
#define K1A_WREG 944
#define K1A_SMEMF (K1A_BASE + K1A_WARPS * K1A_WREG)

__global__ void __launch_bounds__(K1A_WARPS * 32) k1a_kernel(
    const float* __restrict__ eegf,
    const float* __restrict__ fg_w1, const float* __restrict__ fg_b1,
    const float* __restrict__ fg_w2, const float* __restrict__ fg_b2,
    int bsz)
{
    extern __shared__ float sm[];
    float* s_w1T = sm;
    float* s_b1  = sm + 5880;
    float* s_w2  = sm + 5916;
    float* s_b2  = sm + 6164;

    const int tid = threadIdx.x;
    if (blockIdx.x == 0 && tid < 96) g_stats[tid] = 0.0f;
    for (int idx = tid; idx < FGH * FIN; idx += blockDim.x) {
        int j = idx / FIN, i = idx - j * FIN;
        s_w1T[i * FGH + j] = fg_w1[idx];
    }
    if (tid < FGH)  s_b1[tid] = fg_b1[tid];
    for (int idx = tid; idx < FLEN * FGH; idx += blockDim.x) s_w2[idx] = fg_w2[idx];
    if (tid < FLEN) s_b2[tid] = fg_b2[tid];
    __syncthreads();

    const int lane = tid & 31;
    const int wpb  = blockDim.x >> 5;
    const int gw   = blockIdx.x * wpb + (tid >> 5);
    const int nw   = gridDim.x * wpb;

    float* wbase = sm + K1A_BASE + (tid >> 5) * K1A_WREG;
    float2* sXA  = (float2*)wbase;
    float2* sXB  = (float2*)(wbase + 336);
    float2* sH1A = (float2*)(wbase + 672);
    float2* sH1B = (float2*)(wbase + 744);
    float2* sP2A = (float2*)(wbase + 816);
    float2* sP2B = (float2*)(wbase + 876);

    const int npairs = bsz >> 1;
    const int nquads = (npairs + 1) >> 1;

    for (int q = gw; q < nquads; q += nw) {
        const int pA = 2 * q;
        const int pB = (2 * q + 1 < npairs) ? 2 * q + 1 : 2 * q;
        const int bA = 2 * pA, bB = 2 * pB;

        const float* efA0 = eegf + (size_t)bA * FIN;
        const float* efA1 = efA0 + FIN;
        const float* efB0 = eegf + (size_t)bB * FIN;
        const float* efB1 = efB0 + FIN;
        for (int i = lane; i < FIN; i += 32) {
            sXA[i] = make_float2(efA0[i], efA1[i]);
            sXB[i] = make_float2(efB0[i], efB1[i]);
        }
        __syncwarp();

        float2 aA = fdup(s_b1[lane]);
        float2 aB = aA;
        #pragma unroll 4
        for (int i = 0; i < FIN; i++) {
            float2 wv = fdup(s_w1T[i * FGH + lane]);
            aA = f2fma(sXA[i], wv, aA);
            aB = f2fma(sXB[i], wv, aB);
        }
        if (lane < 30) {
            int j = 32 + lane / 10;
            float2 pA2 = make_float2(0.f, 0.f), pB2 = make_float2(0.f, 0.f);
            for (int i = lane % 10; i < FIN; i += 10) {
                float2 wv = fdup(s_w1T[i * FGH + j]);
                pA2 = f2fma(sXA[i], wv, pA2);
                pB2 = f2fma(sXB[i], wv, pB2);
            }
            sP2A[lane] = pA2; sP2B[lane] = pB2;
        }
        sH1A[lane] = ftanha2(aA);
        sH1B[lane] = ftanha2(aB);
        __syncwarp();
        if (lane < 3) {
            float2 tA = fdup(s_b1[32 + lane]);
            float2 tB = tA;
            #pragma unroll
            for (int s = 0; s < 10; s++) {
                tA = f2add(tA, sP2A[lane * 10 + s]);
                tB = f2add(tB, sP2B[lane * 10 + s]);
            }
            sH1A[32 + lane] = ftanha2(tA);
            sH1B[32 + lane] = ftanha2(tB);
        }
        __syncwarp();

        if (lane < FLEN) {
            float2 cA = fdup(s_b2[lane]);
            float2 cB = cA;
            #pragma unroll
            for (int i = 0; i < FGH; i++) {
                float2 wv = fdup(s_w2[lane * FGH + i]);
                cA = f2fma(sH1A[i], wv, cA);
                cB = f2fma(sH1B[i], wv, cB);
            }
            float* gf = g_filt + (size_t)lane * bsz;
            *(float2*)(gf + bA) = ftanh2(cA);   // precise: multiplicative path
            *(float2*)(gf + bB) = ftanh2(cB);
        }
        __syncwarp();
    }
}

// ============ K1b: adaptive filter + conv1 (LDS.128 streamed windows) =======
// R11 config (256,3) + clamped seg-7 start (no nt predication; duplicate
// writes of identical values for t=49..55 are benign)
#define K1B_WARPS 8
#define K1B_BASE 2512
#define K1B_WREG 1404
#define K1B_SMEMF (K1B_BASE + K1B_WARPS * K1B_WREG)

__global__ void __launch_bounds__(K1B_WARPS * 32, 3) k1b_kernel(
    const float* __restrict__ raw,
    const float* __restrict__ enc_w1, const float* __restrict__ enc_b1,
    int bsz)
{
    extern __shared__ float sm[];
    float2* s_cw2 = (float2*)sm;          // [o*78 + c*6 + k] duplicated f2
    float*  s_cb  = sm + 2496;

    const int tid = threadIdx.x;
    for (int idx = tid; idx < EN1 * CH * KW; idx += blockDim.x) {
        int o = idx / (CH * KW), r = idx - o * (CH * KW);
        float w = enc_w1[idx];
        s_cw2[o * 78 + r] = make_float2(w, w);
    }
    if (tid < EN1) s_cb[tid] = enc_b1[tid];
    __syncthreads();

    const int lane = tid & 31;
    const int wpb  = blockDim.x >> 5;
    const int gw   = blockIdx.x * wpb + (tid >> 5);
    const int nw   = gridDim.x * wpb;

    float2* sEegP = (float2*)(sm + K1B_BASE + (tid >> 5) * K1B_WREG);

    float bnS = 0.0f, bnQ = 0.0f;
    const int o   = lane >> 1;          // conv1 out channel
    const int hb  = lane & 1;           // t-half: 0 -> t 0..9, 1 -> t 10..17
    const int tb  = hb * 10;
    const int ns  = 10 - 2 * hb;        // valid outputs this half
    const int cl0 = lane >> 3;          // eeg: channel-part 0..3
    const int seg = lane & 7;           // eeg: 8-t segment
    // clamped start: seg 7 covers t=49..56 (overlap writes identical values)
    const int t0  = (seg == 7) ? (VLEN - 8) : seg * 8;
    const int npairs = bsz >> 1;

    for (int p = gw; p < npairs; p += nw) {
        const int b0 = 2 * p;

        const float* gf = g_filt;
        const float2 f0 = *(const float2*)(gf + 0 * (size_t)bsz + b0);
        const float2 f1 = *(const float2*)(gf + 1 * (size_t)bsz + b0);
        const float2 f2v= *(const float2*)(gf + 2 * (size_t)bsz + b0);
        const float2 f3 = *(const float2*)(gf + 3 * (size_t)bsz + b0);
        const float2 f4 = *(const float2*)(gf + 4 * (size_t)bsz + b0);
        const float2 f5 = *(const float2*)(gf + 5 * (size_t)bsz + b0);
        const float2 f6 = *(const float2*)(gf + 6 * (size_t)bsz + b0);

        // ---- adaptive filter: register sliding window, direct LDG ----
        const float* rb0 = raw + (size_t)b0 * (CH * LRAW);
        #pragma unroll
        for (int ch = 0; ch < 3; ch++) {
            const int c = ch * 4 + cl0;
            const float* r0 = rb0 + c * LRAW + t0;
            const float* r1 = r0 + CH * LRAW;
            float2 w0 = make_float2(r0[0], r1[0]);
            float2 w1 = make_float2(r0[1], r1[1]);
            float2 w2 = make_float2(r0[2], r1[2]);
            float2 w3 = make_float2(r0[3], r1[3]);
            float2 w4 = make_float2(r0[4], r1[4]);
            float2 w5 = make_float2(r0[5], r1[5]);
            float2 w6 = make_float2(r0[6], r1[6]);
            float2* eout = sEegP + c * 58 + t0;
            #pragma unroll
            for (int t = 0; t < 8; t++) {
                float2 a = f2mul(w0, f0);
                a = f2fma(w1, f1, a);  a = f2fma(w2, f2v, a);
                a = f2fma(w3, f3, a);  a = f2fma(w4, f4, a);
                a = f2fma(w5, f5, a);  a = f2fma(w6, f6, a);
                eout[t] = a;
                if (t < 7) {
                    w0 = w1; w1 = w2; w2 = w3; w3 = w4; w4 = w5; w5 = w6;
                    w6 = make_float2(r0[t + 7], r1[t + 7]);
                }
            }
        }
        __syncwarp();

        // ---- conv1: 10 windows/lane, eeg streamed via LDS.128 chunks ----
        float2 accc[10];
        {
            float2 cb2 = fdup(s_cb[o]);
            #pragma unroll
            for (int i = 0; i < 10; i++) accc[i] = cb2;
        }
        #pragma unroll
        for (int c = 0; c < CH; c++) {
            const float4* wq = (const float4*)(s_cw2 + o * 78 + c * 6);
            const float4 wA = wq[0], wB = wq[1], wC = wq[2];
            const float2 W0 = lo2(wA), W1 = hi2(wA), W2 = lo2(wB),
                         W3 = hi2(wB), W4 = lo2(wC), W5 = hi2(wC);
            const float4* e4 = (const float4*)(sEegP + c * 58 + hb * 30);

            #define CONV_STEP(i, E0, E1, E2, E3, E4, E5)                     \
                { float2 a = accc[i];                                        \
                  a = f2fma(E0, W0, a); a = f2fma(E1, W1, a);                \
                  a = f2fma(E2, W2, a); a = f2fma(E3, W3, a);                \
                  a = f2fma(E4, W4, a); a = f2fma(E5, W5, a);                \
                  accc[i] = a; }

            float4 qa = e4[0], qb = e4[1], qc = e4[2];
            CONV_STEP(0, lo2(qa), hi2(qa), lo2(qb), hi2(qb), lo2(qc), hi2(qc))
            float4 qd = e4[3], qe = e4[4];
            CONV_STEP(1, hi2(qb), lo2(qc), hi2(qc), lo2(qd), hi2(qd), lo2(qe))
            float4 qf = e4[5];
            CONV_STEP(2, lo2(qd), hi2(qd), lo2(qe), hi2(qe), lo2(qf), hi2(qf))
            float4 qg = e4[6], qh = e4[7];
            CONV_STEP(3, hi2(qe), lo2(qf), hi2(qf), lo2(qg), hi2(qg), lo2(qh))
            float4 qi = e4[8];
            CONV_STEP(4, lo2(qg), hi2(qg), lo2(qh), hi2(qh), lo2(qi), hi2(qi))
            float4 qj = e4[9], qk = e4[10];
            CONV_STEP(5, hi2(qh), lo2(qi), hi2(qi), lo2(qj), hi2(qj), lo2(qk))
            float4 ql = e4[11];
            CONV_STEP(6, lo2(qj), hi2(qj), lo2(qk), hi2(qk), lo2(ql), hi2(ql))
            float4 qm = e4[12], qn = e4[13];
            CONV_STEP(7, hi2(qk), lo2(ql), hi2(ql), lo2(qm), hi2(qm), lo2(qn))
            float4 qo = e4[14];
            CONV_STEP(8, lo2(qm), hi2(qm), lo2(qn), hi2(qn), lo2(qo), hi2(qo))
            float4 qp = e4[15], qq = e4[16];
            CONV_STEP(9, hi2(qn), lo2(qo), hi2(qo), lo2(qp), hi2(qp), lo2(qq))
            #undef CONV_STEP
        }

        float2* gy = g_y1p + (size_t)p * Y1N;
        #pragma unroll
        for (int i = 0; i < 10; i++) {
            if (i < ns) {
                float2 v = accc[i];
                gy[o * L1 + tb + i] = v;
                bnS += v.x + v.y;
                bnQ = fmaf(v.x, v.x, fmaf(v.y, v.y, bnQ));
            }
        }
        __syncwarp();
    }
    bnS += __shfl_down_sync(0xffffffffu, bnS, 1);
    bnQ += __shfl_down_sync(0xffffffffu, bnQ, 1);
    if ((lane & 1) == 0) {
        atomicAdd(&g_stats[o], bnS);
        atomicAdd(&g_stats[EN1 + o], bnQ);
    }
}

// -------- K2: BN1+tanh (float4), conv2 over two pairs, BN2 partials ---------
#define K2_WARPS 8
#define K2_SMEMF (3200 + K2_WARPS * 1152)

__global__ void __launch_bounds__(K2_WARPS * 32, 3) k2_kernel(
    const float* __restrict__ enc_w2, const float* __restrict__ enc_b2,
    const float* __restrict__ bn1_g, const float* __restrict__ bn1_b,
    int bsz)
{
    extern __shared__ float sm[];
    float*  s_w   = sm;                      // scalar [r*32 + o]
    float2* s_bd  = (float2*)(sm + 3072);
    float2* s_scP = (float2*)(sm + 3136);
    float2* s_shP = (float2*)(sm + 3168);

    const int tid = threadIdx.x;
    for (int idx = tid; idx < EN2 * EN1 * KW; idx += blockDim.x) {
        int o = idx / (EN1 * KW), r = idx - o * (EN1 * KW);
        s_w[r * 32 + o] = enc_w2[idx];
    }
    if (tid < EN2) s_bd[tid] = fdup(enc_b2[tid]);
    if (tid < EN1) {
        float inv = 1.0f / ((float)bsz * (float)L1);
        float m = g_stats[tid] * inv;
        float v = g_stats[EN1 + tid] * inv - m * m;
        float r = rsqrtf(v + 1e-5f);
        float sc = bn1_g[tid] * r;
        s_scP[tid] = fdup(sc);
        s_shP[tid] = fdup(bn1_b[tid] - m * sc);
    }
    __syncthreads();

    const int lane = tid & 31;
    const int w    = tid >> 5;
    const int wpb  = blockDim.x >> 5;
    const int gw   = blockIdx.x * wpb + w;
    const int nw   = gridDim.x * wpb;
    float2* sHP0 = (float2*)(sm + 3200) + w * 576;
    float2* sHP1 = sHP0 + 288;

    float bnS = 0.f, bnQ = 0.f;
    const int o = lane;
    const int npairs = bsz >> 1;
    const int nquads = npairs >> 1;

    for (int q = gw; q < nquads; q += nw) {
        const int p0 = 2 * q, p1 = 2 * q + 1;
        const float4* gy0 = (const float4*)(g_y1p + (size_t)p0 * Y1N);
        const float4* gy1 = (const float4*)(g_y1p + (size_t)p1 * Y1N);
        float4* d0 = (float4*)sHP0;
        float4* d1 = (float4*)sHP1;
        #pragma unroll
        for (int j = 0; j < 5; j++) {
            int idx4 = lane + 32 * j;
            if (idx4 < 144) {
                unsigned c = (unsigned)idx4 / 9u;
                float2 sc = s_scP[c], sh = s_shP[c];
                float4 q0 = gy0[idx4], q1 = gy1[idx4];
                float2 a0 = ftanha2(f2fma(make_float2(q0.x, q0.y), sc, sh));
                float2 a1 = ftanha2(f2fma(make_float2(q0.z, q0.w), sc, sh));
                float2 b0 = ftanha2(f2fma(make_float2(q1.x, q1.y), sc, sh));
                float2 b1 = ftanha2(f2fma(make_float2(q1.z, q1.w), sc, sh));
                d0[idx4] = make_float4(a0.x, a0.y, a1.x, a1.y);
                d1[idx4] = make_float4(b0.x, b0.y, b1.x, b1.y);
            }
        }
        __syncwarp();

        float2 acc0[L2], acc1[L2];
        {
            float2 b2 = s_bd[o];
            #pragma unroll
            for (int t = 0; t < L2; t++) { acc0[t] = b2; acc1[t] = b2; }
        }
        #pragma unroll
        for (int c = 0; c < EN1; c++) {
            const float* wp = s_w + (c * KW) * 32 + o;
            float2 W[KW];
            #pragma unroll
            for (int k = 0; k < KW; k++) W[k] = fdup(wp[k * 32]);

            const float4* h40 = reinterpret_cast<const float4*>(sHP0 + c * L1);
            const float4* h41 = reinterpret_cast<const float4*>(sHP1 + c * L1);
            float2 g0[L1], g1[L1];
            #pragma unroll
            for (int x = 0; x < 9; x++) {
                float4 q0 = h40[x], q1 = h41[x];
                g0[2 * x]     = make_float2(q0.x, q0.y);
                g0[2 * x + 1] = make_float2(q0.z, q0.w);
                g1[2 * x]     = make_float2(q1.x, q1.y);
                g1[2 * x + 1] = make_float2(q1.z, q1.w);
            }
            #pragma unroll
            for (int k = 0; k < KW; k++) {
                #pragma unroll
                for (int t = 0; t < L2; t++) {
                    acc0[t] = f2fma(g0[3 * t + k], W[k], acc0[t]);
                    acc1[t] = f2fma(g1[3 * t + k], W[k], acc1[t]);
                }
            }
        }
        float2* g20 = g_y2p + (size_t)p0 * Y2N;
        float2* g21 = g_y2p + (size_t)p1 * Y2N;
        #pragma unroll
        for (int t = 0; t < L2; t++) {
            g20[o * L2 + t] = acc0[t];
            g21[o * L2 + t] = acc1[t];
            bnS += acc0[t].x + acc0[t].y + acc1[t].x + acc1[t].y;
            bnQ = fmaf(acc0[t].x, acc0[t].x, fmaf(acc0[t].y, acc0[t].y, bnQ));
            bnQ = fmaf(acc1[t].x, acc1[t].x, fmaf(acc1[t].y, acc1[t].y, bnQ));
        }
        __syncwarp();
    }
    atomicAdd(&g_stats[32 + o], bnS);
    atomicAdd(&g_stats[64 + o], bnQ);
}

// ---- K3: BN2+tanh, heads, reparam, decoder — loop-invariants in registers --
#define K3_WPB 8
__global__ void __launch_bounds__(K3_WPB * 32) k3_kernel(
    const float* __restrict__ eps,
    const float* __restrict__ mu_w, const float* __restrict__ mu_b,
    const float* __restrict__ lv_w, const float* __restrict__ lv_b,
    const float* __restrict__ de_w1, const float* __restrict__ de_b1,
    const float* __restrict__ de_w2, const float* __restrict__ de_b2,
    const float* __restrict__ bn2_g, const float* __restrict__ bn2_b,
    float* __restrict__ out, int bsz)
{
    __shared__ float  s_dw1[DEH * 2], s_db1[DEH];
    __shared__ float2 s_dw2d[DEOUT * DEH];
    __shared__ float2 s_db2d[DEOUT];
    __shared__ float  s_sc[EN2], s_sh[EN2];
    __shared__ float2 s_d[K3_WPB][12];

    const int tid = threadIdx.x;
    for (int i = tid; i < DEH * 2; i += blockDim.x) s_dw1[i] = de_w1[i];
    if (tid < DEH) s_db1[tid] = de_b1[tid];
    for (int i = tid; i < DEOUT * DEH; i += blockDim.x) s_dw2d[i] = fdup(de_w2[i]);
    if (tid < DEOUT) s_db2d[tid] = fdup(de_b2[tid]);
    if (tid < EN2) {
        float inv = 1.0f / ((float)bsz * (float)L2);
        float m = g_stats[32 + tid] * inv;
        float v = g_stats[64 + tid] * inv - m * m;
        float r = rsqrtf(v + 1e-5f);
        float sc = bn2_g[tid] * r;
        s_sc[tid] = sc;
        s_sh[tid] = bn2_b[tid] - m * sc;
    }
    __syncthreads();

    const int lane = tid & 31;
    const int w    = tid >> 5;

    float2 rmu0[5], rmu1[5], rlv0[5], rlv1[5], rsc[5], rsh[5];
    #pragma unroll
    for (int j = 0; j < 5; j++) {
        int i = lane + 32 * j;
        int c = i / L2;
        rmu0[j] = fdup(mu_w[i]);       rmu1[j] = fdup(mu_w[Y2N + i]);
        rlv0[j] = fdup(lv_w[i]);       rlv1[j] = fdup(lv_w[Y2N + i]);
        rsc[j]  = fdup(s_sc[c]);       rsh[j]  = fdup(s_sh[c]);
    }
    const float mub0 = mu_b[0], mub1 = mu_b[1];
    const float lvb0 = lv_b[0], lvb1 = lv_b[1];

    const int wpb  = blockDim.x >> 5;
    const int gw   = blockIdx.x * wpb + w;
    const int nw   = gridDim.x * wpb;
    const int npairs = bsz >> 1;

    float* outO = out;
    float* outM = out + (size_t)bsz * DEOUT;
    float* outV = out + (size_t)bsz * (DEOUT + 2);

    for (int p = gw; p < npairs; p += nw) {
        const int b0 = 2 * p;
        const float2* gy = g_y2p + (size_t)p * Y2N;
        float2 pm0 = make_float2(0.f, 0.f), pm1 = pm0, pl0 = pm0, pl1 = pm0;
        #pragma unroll
        for (int j = 0; j < 5; j++) {
            float2 v = ftanha2(f2fma(gy[lane + 32 * j], rsc[j], rsh[j]));
            pm0 = f2fma(v, rmu0[j], pm0);
            pm1 = f2fma(v, rmu1[j], pm1);
            pl0 = f2fma(v, rlv0[j], pl0);
            pl1 = f2fma(v, rlv1[j], pl1);
        }
        #pragma unroll
        for (int off = 16; off > 0; off >>= 1) {
            pm0.x += __shfl_xor_sync(0xffffffffu, pm0.x, off);
            pm0.y += __shfl_xor_sync(0xffffffffu, pm0.y, off);
            pm1.x += __shfl_xor_sync(0xffffffffu, pm1.x, off);
            pm1.y += __shfl_xor_sync(0xffffffffu, pm1.y, off);
            pl0.x += __shfl_xor_sync(0xffffffffu, pl0.x, off);
            pl0.y += __shfl_xor_sync(0xffffffffu, pl0.y, off);
            pl1.x += __shfl_xor_sync(0xffffffffu, pl1.x, off);
            pl1.y += __shfl_xor_sync(0xffffffffu, pl1.y, off);
        }
        float2 mu0 = f2add(pm0, fdup(mub0));
        float2 mu1 = f2add(pm1, fdup(mub1));
        float2 lv0 = f2add(pl0, fdup(lvb0));
        float2 lv1 = f2add(pl1, fdup(lvb1));
        const float4 ev = *(const float4*)(eps + (size_t)b0 * 2);
        float2 z0 = make_float2(fmaf(ev.x, __expf(0.5f * lv0.x), mu0.x),
                                fmaf(ev.z, __expf(0.5f * lv0.y), mu0.y));
        float2 z1 = make_float2(fmaf(ev.y, __expf(0.5f * lv1.x), mu1.x),
                                fmaf(ev.w, __expf(0.5f * lv1.y), mu1.y));

        if (lane < DEH) {
            float2 a = f2fma(z0, fdup(s_dw1[lane * 2]),
                       f2fma(z1, fdup(s_dw1[lane * 2 + 1]), fdup(s_db1[lane])));
            s_d[w][lane] = ftanha2(a);
        }
        __syncwarp();
        float2 dreg[DEH];
        #pragma unroll
        for (int j = 0; j < DEH; j++) dreg[j] = s_d[w][j];

        float* oo0 = outO + (size_t)b0 * DEOUT;
        float* oo1 = oo0 + DEOUT;
        for (int k = lane; k < DEOUT; k += 32) {
            float2 a = s_db2d[k];
            #pragma unroll
            for (int j = 0; j < DEH; j++)
                a = f2fma(dreg[j], s_dw2d[k * DEH + j], a);
            a = ftanh2(a);   // precise: final output
            oo0[k] = a.x;
            oo1[k] = a.y;
        }
        if (lane == 0) {
            *(float2*)(outM + (size_t)b0 * 2)       = make_float2(mu0.x, mu1.x);
            *(float2*)(outM + (size_t)(b0 + 1) * 2) = make_float2(mu0.y, mu1.y);
            *(float2*)(outV + (size_t)b0 * 2)       = make_float2(lv0.x, lv1.x);
            *(float2*)(outV + (size_t)(b0 + 1) * 2) = make_float2(lv0.y, lv1.y);
        }
        __syncwarp();
    }
}

extern "C" void kernel_launch(void* const* d_in, const int* in_sizes, int n_in,
                              void* d_out, int out_size)
{
    const float* raw    = (const float*)d_in[0];
    const float* eegf   = (const float*)d_in[1];
    const float* eps    = (const float*)d_in[2];
    const float* fg_w1  = (const float*)d_in[3];
    const float* fg_b1  = (const float*)d_in[4];
    const float* fg_w2  = (const float*)d_in[5];
    const float* fg_b2  = (const float*)d_in[6];
    const float* enc_w1 = (const float*)d_in[7];
    const float* enc_b1 = (const float*)d_in[8];
    const float* bn1_g  = (const float*)d_in[9];
    const float* bn1_b  = (const float*)d_in[10];
    const float* enc_w2 = (const float*)d_in[11];
    const float* enc_b2 = (const float*)d_in[12];
    const float* bn2_g  = (const float*)d_in[13];
    const float* bn2_b  = (const float*)d_in[14];
    const float* mu_w   = (const float*)d_in[15];
    const float* mu_b   = (const float*)d_in[16];
    const float* lv_w   = (const float*)d_in[17];
    const float* lv_b   = (const float*)d_in[18];
    const float* de_w1  = (const float*)d_in[19];
    const float* de_b1  = (const float*)d_in[20];
    const float* de_w2  = (const float*)d_in[21];
    const float* de_b2  = (const float*)d_in[22];

    int bsz = in_sizes[0] / (CH * LRAW);

    size_t smemA = (size_t)K1A_SMEMF * sizeof(float);
    cudaFuncSetAttribute((const void*)k1a_kernel,
                         cudaFuncAttributeMaxDynamicSharedMemorySize, (int)smemA);
    k1a_kernel<<<296, K1A_WARPS * 32, smemA>>>(eegf, fg_w1, fg_b1, fg_w2, fg_b2, bsz);

    size_t smemB = (size_t)K1B_SMEMF * sizeof(float);
    cudaFuncSetAttribute((const void*)k1b_kernel,
                         cudaFuncAttributeMaxDynamicSharedMemorySize, (int)smemB);
    k1b_kernel<<<444, K1B_WARPS * 32, smemB>>>(raw, enc_w1, enc_b1, bsz);

    size_t smem2 = (size_t)K2_SMEMF * sizeof(float);
    cudaFuncSetAttribute((const void*)k2_kernel,
                         cudaFuncAttributeMaxDynamicSharedMemorySize, (int)smem2);
    k2_kernel<<<444, K2_WARPS * 32, smem2>>>(enc_w2, enc_b2, bn1_g, bn1_b, bsz);

    k3_kernel<<<444, K3_WPB * 32>>>(eps, mu_w, mu_b, lv_w, lv_b,
                                    de_w1, de_b1, de_w2, de_b2,
                                    bn2_g, bn2_b, (float*)d_out, bsz);
}

// round 15
// speedup vs baseline: 1.0767x; 1.0464x over previous
#include <cuda_runtime.h>
#include <math.h>

#define BMAX 65536
#define CH 12
#define LRAW 63
#define FLEN 7
#define VLEN 57
#define FIN 168
#define FGH 35
#define EN1 16
#define EN2 32
#define KW 6
#define L1 18
#define L2 5
#define Y1N (EN1 * L1)   // 288
#define Y2N (EN2 * L2)   // 160
#define DEH 10
#define DEOUT 50

// global scratch (allocation-free: __device__ globals)
__device__ float g_filt[(size_t)FLEN * BMAX];         // transposed [k][B]
__device__ float2 g_y1p[(size_t)(BMAX / 2) * Y1N];
__device__ float2 g_y2p[(size_t)(BMAX / 2) * Y2N];
__device__ float g_stats[96];

// ---------------- packed fp32x2 helpers (sm_103a FFMA2 path) ----------------
__device__ __forceinline__ float2 f2fma(float2 a, float2 b, float2 c) {
    unsigned long long ua = reinterpret_cast<unsigned long long&>(a);
    unsigned long long ub = reinterpret_cast<unsigned long long&>(b);
    unsigned long long uc = reinterpret_cast<unsigned long long&>(c);
    unsigned long long ud;
    asm("fma.rn.f32x2 %0, %1, %2, %3;" : "=l"(ud) : "l"(ua), "l"(ub), "l"(uc));
    return reinterpret_cast<float2&>(ud);
}
__device__ __forceinline__ float2 f2mul(float2 a, float2 b) {
    unsigned long long ua = reinterpret_cast<unsigned long long&>(a);
    unsigned long long ub = reinterpret_cast<unsigned long long&>(b);
    unsigned long long ud;
    asm("mul.rn.f32x2 %0, %1, %2;" : "=l"(ud) : "l"(ua), "l"(ub));
    return reinterpret_cast<float2&>(ud);
}
__device__ __forceinline__ float2 f2add(float2 a, float2 b) {
    unsigned long long ua = reinterpret_cast<unsigned long long&>(a);
    unsigned long long ub = reinterpret_cast<unsigned long long&>(b);
    unsigned long long ud;
    asm("add.rn.f32x2 %0, %1, %2;" : "=l"(ud) : "l"(ua), "l"(ub));
    return reinterpret_cast<float2&>(ud);
}
__device__ __forceinline__ float2 fdup(float x) { return make_float2(x, x); }
__device__ __forceinline__ float2 lo2(float4 q) { return make_float2(q.x, q.y); }
__device__ __forceinline__ float2 hi2(float4 q) { return make_float2(q.z, q.w); }

// precise tanh: (e^{2x}-1)/(e^{2x}+1), rel err ~1e-6 (output-facing paths)
__device__ __forceinline__ float ftanh(float x) {
    float xc = fminf(fmaxf(x, -9.0f), 9.0f);
    float t  = __expf(xc + xc);
    return __fdividef(t - 1.0f, t + 1.0f);
}
__device__ __forceinline__ float2 ftanh2(float2 v) {
    return make_float2(ftanh(v.x), ftanh(v.y));
}
// HW tanh (sm_75+ MUFU.TANH), max rel err ~2^-11 — internal layers only
__device__ __forceinline__ float ftanha(float x) {
    float y;
    asm("tanh.approx.f32 %0, %1;" : "=f"(y) : "f"(x));
    return y;
}
__device__ __forceinline__ float2 ftanha2(float2 v) {
    return make_float2(ftanha(v.x), ftanha(v.y));
}

// ================= K1a: filter generator, 4 samples per warp ================
#define K1A_WARPS 16
#define K1A_BASE 6172
#define K1A_WREG 944
#define K1A_SMEMF (K1A_BASE + K1A_WARPS * K1A_WREG)

__global__ void __launch_bounds__(K1A_WARPS * 32) k1a_kernel(
    const float* __restrict__ eegf,
    const float* __restrict__ fg_w1, const float* __restrict__ fg_b1,
    const float* __restrict__ fg_w2, const float* __restrict__ fg_b2,
    int bsz)
{
    extern __shared__ float sm[];
    float* s_w1T = sm;
    float* s_b1  = sm + 5880;
    float* s_w2  = sm + 5916;
    float* s_b2  = sm + 6164;

    const int tid = threadIdx.x;
    if (blockIdx.x == 0 && tid < 96) g_stats[tid] = 0.0f;
    for (int idx = tid; idx < FGH * FIN; idx += blockDim.x) {
        int j = idx / FIN, i = idx - j * FIN;
        s_w1T[i * FGH + j] = fg_w1[idx];
    }
    if (tid < FGH)  s_b1[tid] = fg_b1[tid];
    for (int idx = tid; idx < FLEN * FGH; idx += blockDim.x) s_w2[idx] = fg_w2[idx];
    if (tid < FLEN) s_b2[tid] = fg_b2[tid];
    __syncthreads();

    const int lane = tid & 31;
    const int wpb  = blockDim.x >> 5;
    const int gw   = blockIdx.x * wpb + (tid >> 5);
    const int nw   = gridDim.x * wpb;

    float* wbase = sm + K1A_BASE + (tid >> 5) * K1A_WREG;
    float2* sXA  = (float2*)wbase;
    float2* sXB  = (float2*)(wbase + 336);
    float2* sH1A = (float2*)(wbase + 672);
    float2* sH1B = (float2*)(wbase + 744);
    float2* sP2A = (float2*)(wbase + 816);
    float2* sP2B = (float2*)(wbase + 876);

    const int npairs = bsz >> 1;
    const int nquads = (npairs + 1) >> 1;

    for (int q = gw; q < nquads; q += nw) {
        const int pA = 2 * q;
        const int pB = (2 * q + 1 < npairs) ? 2 * q + 1 : 2 * q;
        const int bA = 2 * pA, bB = 2 * pB;

        const float* efA0 = eegf + (size_t)bA * FIN;
        const float* efA1 = efA0 + FIN;
        const float* efB0 = eegf + (size_t)bB * FIN;
        const float* efB1 = efB0 + FIN;
        for (int i = lane; i < FIN; i += 32) {
            sXA[i] = make_float2(efA0[i], efA1[i]);
            sXB[i] = make_float2(efB0[i], efB1[i]);
        }
        __syncwarp();

        float2 aA = fdup(s_b1[lane]);
        float2 aB = aA;
        #pragma unroll 4
        for (int i = 0; i < FIN; i++) {
            float2 wv = fdup(s_w1T[i * FGH + lane]);
            aA = f2fma(sXA[i], wv, aA);
            aB = f2fma(sXB[i], wv, aB);
        }
        if (lane < 30) {
            int j = 32 + lane / 10;
            float2 pA2 = make_float2(0.f, 0.f), pB2 = make_float2(0.f, 0.f);
            for (int i = lane % 10; i < FIN; i += 10) {
                float2 wv = fdup(s_w1T[i * FGH + j]);
                pA2 = f2fma(sXA[i], wv, pA2);
                pB2 = f2fma(sXB[i], wv, pB2);
            }
            sP2A[lane] = pA2; sP2B[lane] = pB2;
        }
        sH1A[lane] = ftanha2(aA);
        sH1B[lane] = ftanha2(aB);
        __syncwarp();
        if (lane < 3) {
            float2 tA = fdup(s_b1[32 + lane]);
            float2 tB = tA;
            #pragma unroll
            for (int s = 0; s < 10; s++) {
                tA = f2add(tA, sP2A[lane * 10 + s]);
                tB = f2add(tB, sP2B[lane * 10 + s]);
            }
            sH1A[32 + lane] = ftanha2(tA);
            sH1B[32 + lane] = ftanha2(tB);
        }
        __syncwarp();

        if (lane < FLEN) {
            float2 cA = fdup(s_b2[lane]);
            float2 cB = cA;
            #pragma unroll
            for (int i = 0; i < FGH; i++) {
                float2 wv = fdup(s_w2[lane * FGH + i]);
                cA = f2fma(sH1A[i], wv, cA);
                cB = f2fma(sH1B[i], wv, cB);
            }
            float* gf = g_filt + (size_t)lane * bsz;
            *(float2*)(gf + bA) = ftanh2(cA);   // precise: multiplicative path
            *(float2*)(gf + bB) = ftanh2(cB);
        }
        __syncwarp();
    }
}

// ============ K1b: adaptive filter + conv1 (LDS.128 streamed windows) =======
// champion config (R11): (256,3), rolling window, nt predication
#define K1B_WARPS 8
#define K1B_BASE 2512
#define K1B_WREG 1404
#define K1B_SMEMF (K1B_BASE + K1B_WARPS * K1B_WREG)

__global__ void __launch_bounds__(K1B_WARPS * 32, 3) k1b_kernel(
    const float* __restrict__ raw,
    const float* __restrict__ enc_w1, const float* __restrict__ enc_b1,
    int bsz)
{
    extern __shared__ float sm[];
    float2* s_cw2 = (float2*)sm;          // [o*78 + c*6 + k] duplicated f2
    float*  s_cb  = sm + 2496;

    const int tid = threadIdx.x;
    for (int idx = tid; idx < EN1 * CH * KW; idx += blockDim.x) {
        int o = idx / (CH * KW), r = idx - o * (CH * KW);
        float w = enc_w1[idx];
        s_cw2[o * 78 + r] = make_float2(w, w);
    }
    if (tid < EN1) s_cb[tid] = enc_b1[tid];
    __syncthreads();

    const int lane = tid & 31;
    const int wpb  = blockDim.x >> 5;
    const int gw   = blockIdx.x * wpb + (tid >> 5);
    const int nw   = gridDim.x * wpb;

    float2* sEegP = (float2*)(sm + K1B_BASE + (tid >> 5) * K1B_WREG);

    float bnS = 0.0f, bnQ = 0.0f;
    const int o   = lane >> 1;          // conv1 out channel
    const int hb  = lane & 1;           // t-half: 0 -> t 0..9, 1 -> t 10..17
    const int tb  = hb * 10;
    const int ns  = 10 - 2 * hb;        // valid outputs this half
    const int cl0 = lane >> 3;          // eeg: channel-part 0..3
    const int seg = lane & 7;           // eeg: 8-t segment
    const int t0  = seg * 8;
    const int nt  = (t0 + 8 <= VLEN) ? 8 : (VLEN - t0);
    const int npairs = bsz >> 1;

    for (int p = gw; p < npairs; p += nw) {
        const int b0 = 2 * p;

        const float* gf = g_filt;
        const float2 f0 = *(const float2*)(gf + 0 * (size_t)bsz + b0);
        const float2 f1 = *(const float2*)(gf + 1 * (size_t)bsz + b0);
        const float2 f2v= *(const float2*)(gf + 2 * (size_t)bsz + b0);
        const float2 f3 = *(const float2*)(gf + 3 * (size_t)bsz + b0);
        const float2 f4 = *(const float2*)(gf + 4 * (size_t)bsz + b0);
        const float2 f5 = *(const float2*)(gf + 5 * (size_t)bsz + b0);
        const float2 f6 = *(const float2*)(gf + 6 * (size_t)bsz + b0);

        // ---- adaptive filter: register sliding window, direct LDG ----
        const float* rb0 = raw + (size_t)b0 * (CH * LRAW);
        #pragma unroll
        for (int ch = 0; ch < 3; ch++) {
            const int c = ch * 4 + cl0;
            const float* r0 = rb0 + c * LRAW + t0;
            const float* r1 = r0 + CH * LRAW;
            float2 w0 = make_float2(r0[0], r1[0]);
            float2 w1 = make_float2(r0[1], r1[1]);
            float2 w2 = make_float2(r0[2], r1[2]);
            float2 w3 = make_float2(r0[3], r1[3]);
            float2 w4 = make_float2(r0[4], r1[4]);
            float2 w5 = make_float2(r0[5], r1[5]);
            float2 w6 = make_float2(r0[6], r1[6]);
            float2* eout = sEegP + c * 58 + t0;
            #pragma unroll
            for (int t = 0; t < 8; t++) {
                if (t < nt) {
                    float2 a = f2mul(w0, f0);
                    a = f2fma(w1, f1, a);  a = f2fma(w2, f2v, a);
                    a = f2fma(w3, f3, a);  a = f2fma(w4, f4, a);
                    a = f2fma(w5, f5, a);  a = f2fma(w6, f6, a);
                    eout[t] = a;
                    if (t < 7) {
                        w0 = w1; w1 = w2; w2 = w3; w3 = w4; w4 = w5; w5 = w6;
                        w6 = make_float2(r0[t + 7], r1[t + 7]);
                    }
                }
            }
        }
        __syncwarp();

        // ---- conv1: 10 windows/lane, eeg streamed via LDS.128 chunks ----
        float2 accc[10];
        {
            float2 cb2 = fdup(s_cb[o]);
            #pragma unroll
            for (int i = 0; i < 10; i++) accc[i] = cb2;
        }
        #pragma unroll
        for (int c = 0; c < CH; c++) {
            const float4* wq = (const float4*)(s_cw2 + o * 78 + c * 6);
            const float4 wA = wq[0], wB = wq[1], wC = wq[2];
            const float2 W0 = lo2(wA), W1 = hi2(wA), W2 = lo2(wB),
                         W3 = hi2(wB), W4 = lo2(wC), W5 = hi2(wC);
            const float4* e4 = (const float4*)(sEegP + c * 58 + hb * 30);

            #define CONV_STEP(i, E0, E1, E2, E3, E4, E5)                     \
                { float2 a = accc[i];                                        \
                  a = f2fma(E0, W0, a); a = f2fma(E1, W1, a);                \
                  a = f2fma(E2, W2, a); a = f2fma(E3, W3, a);                \
                  a = f2fma(E4, W4, a); a = f2fma(E5, W5, a);                \
                  accc[i] = a; }

            float4 qa = e4[0], qb = e4[1], qc = e4[2];
            CONV_STEP(0, lo2(qa), hi2(qa), lo2(qb), hi2(qb), lo2(qc), hi2(qc))
            float4 qd = e4[3], qe = e4[4];
            CONV_STEP(1, hi2(qb), lo2(qc), hi2(qc), lo2(qd), hi2(qd), lo2(qe))
            float4 qf = e4[5];
            CONV_STEP(2, lo2(qd), hi2(qd), lo2(qe), hi2(qe), lo2(qf), hi2(qf))
            float4 qg = e4[6], qh = e4[7];
            CONV_STEP(3, hi2(qe), lo2(qf), hi2(qf), lo2(qg), hi2(qg), lo2(qh))
            float4 qi = e4[8];
            CONV_STEP(4, lo2(qg), hi2(qg), lo2(qh), hi2(qh), lo2(qi), hi2(qi))
            float4 qj = e4[9], qk = e4[10];
            CONV_STEP(5, hi2(qh), lo2(qi), hi2(qi), lo2(qj), hi2(qj), lo2(qk))
            float4 ql = e4[11];
            CONV_STEP(6, lo2(qj), hi2(qj), lo2(qk), hi2(qk), lo2(ql), hi2(ql))
            float4 qm = e4[12], qn = e4[13];
            CONV_STEP(7, hi2(qk), lo2(ql), hi2(ql), lo2(qm), hi2(qm), lo2(qn))
            float4 qo = e4[14];
            CONV_STEP(8, lo2(qm), hi2(qm), lo2(qn), hi2(qn), lo2(qo), hi2(qo))
            float4 qp = e4[15], qq = e4[16];
            CONV_STEP(9, hi2(qn), lo2(qo), hi2(qo), lo2(qp), hi2(qp), lo2(qq))
            #undef CONV_STEP
        }

        float2* gy = g_y1p + (size_t)p * Y1N;
        #pragma unroll
        for (int i = 0; i < 10; i++) {
            if (i < ns) {
                float2 v = accc[i];
                gy[o * L1 + tb + i] = v;
                bnS += v.x + v.y;
                bnQ = fmaf(v.x, v.x, fmaf(v.y, v.y, bnQ));
            }
        }
        __syncwarp();
    }
    bnS += __shfl_down_sync(0xffffffffu, bnS, 1);
    bnQ += __shfl_down_sync(0xffffffffu, bnQ, 1);
    if ((lane & 1) == 0) {
        atomicAdd(&g_stats[o], bnS);
        atomicAdd(&g_stats[EN1 + o], bnQ);
    }
}

// -------- K2: BN1+tanh (float4), conv2 over two pairs, BN2 partials ---------
#define K2_WARPS 8
#define K2_SMEMF (3200 + K2_WARPS * 1152)

__global__ void __launch_bounds__(K2_WARPS * 32, 3) k2_kernel(
    const float* __restrict__ enc_w2, const float* __restrict__ enc_b2,
    const float* __restrict__ bn1_g, const float* __restrict__ bn1_b,
    int bsz)
{
    extern __shared__ float sm[];
    float*  s_w   = sm;                      // scalar [r*32 + o]
    float2* s_bd  = (float2*)(sm + 3072);
    float2* s_scP = (float2*)(sm + 3136);
    float2* s_shP = (float2*)(sm + 3168);

    const int tid = threadIdx.x;
    for (int idx = tid; idx < EN2 * EN1 * KW; idx += blockDim.x) {
        int o = idx / (EN1 * KW), r = idx - o * (EN1 * KW);
        s_w[r * 32 + o] = enc_w2[idx];
    }
    if (tid < EN2) s_bd[tid] = fdup(enc_b2[tid]);
    if (tid < EN1) {
        float inv = 1.0f / ((float)bsz * (float)L1);
        float m = g_stats[tid] * inv;
        float v = g_stats[EN1 + tid] * inv - m * m;
        float r = rsqrtf(v + 1e-5f);
        float sc = bn1_g[tid] * r;
        s_scP[tid] = fdup(sc);
        s_shP[tid] = fdup(bn1_b[tid] - m * sc);
    }
    __syncthreads();

    const int lane = tid & 31;
    const int w    = tid >> 5;
    const int wpb  = blockDim.x >> 5;
    const int gw   = blockIdx.x * wpb + w;
    const int nw   = gridDim.x * wpb;
    float2* sHP0 = (float2*)(sm + 3200) + w * 576;
    float2* sHP1 = sHP0 + 288;

    float bnS = 0.f, bnQ = 0.f;
    const int o = lane;
    const int npairs = bsz >> 1;
    const int nquads = npairs >> 1;

    for (int q = gw; q < nquads; q += nw) {
        const int p0 = 2 * q, p1 = 2 * q + 1;
        const float4* gy0 = (const float4*)(g_y1p + (size_t)p0 * Y1N);
        const float4* gy1 = (const float4*)(g_y1p + (size_t)p1 * Y1N);
        float4* d0 = (float4*)sHP0;
        float4* d1 = (float4*)sHP1;
        #pragma unroll
        for (int j = 0; j < 5; j++) {
            int idx4 = lane + 32 * j;
            if (idx4 < 144) {
                unsigned c = (unsigned)idx4 / 9u;
                float2 sc = s_scP[c], sh = s_shP[c];
                float4 q0 = gy0[idx4], q1 = gy1[idx4];
                float2 a0 = ftanha2(f2fma(make_float2(q0.x, q0.y), sc, sh));
                float2 a1 = ftanha2(f2fma(make_float2(q0.z, q0.w), sc, sh));
                float2 b0 = ftanha2(f2fma(make_float2(q1.x, q1.y), sc, sh));
                float2 b1 = ftanha2(f2fma(make_float2(q1.z, q1.w), sc, sh));
                d0[idx4] = make_float4(a0.x, a0.y, a1.x, a1.y);
                d1[idx4] = make_float4(b0.x, b0.y, b1.x, b1.y);
            }
        }
        __syncwarp();

        float2 acc0[L2], acc1[L2];
        {
            float2 b2 = s_bd[o];
            #pragma unroll
            for (int t = 0; t < L2; t++) { acc0[t] = b2; acc1[t] = b2; }
        }
        #pragma unroll
        for (int c = 0; c < EN1; c++) {
            const float* wp = s_w + (c * KW) * 32 + o;
            float2 W[KW];
            #pragma unroll
            for (int k = 0; k < KW; k++) W[k] = fdup(wp[k * 32]);

            const float4* h40 = reinterpret_cast<const float4*>(sHP0 + c * L1);
            const float4* h41 = reinterpret_cast<const float4*>(sHP1 + c * L1);
            float2 g0[L1], g1[L1];
            #pragma unroll
            for (int x = 0; x < 9; x++) {
                float4 q0 = h40[x], q1 = h41[x];
                g0[2 * x]     = make_float2(q0.x, q0.y);
                g0[2 * x + 1] = make_float2(q0.z, q0.w);
                g1[2 * x]     = make_float2(q1.x, q1.y);
                g1[2 * x + 1] = make_float2(q1.z, q1.w);
            }
            #pragma unroll
            for (int k = 0; k < KW; k++) {
                #pragma unroll
                for (int t = 0; t < L2; t++) {
                    acc0[t] = f2fma(g0[3 * t + k], W[k], acc0[t]);
                    acc1[t] = f2fma(g1[3 * t + k], W[k], acc1[t]);
                }
            }
        }
        float2* g20 = g_y2p + (size_t)p0 * Y2N;
        float2* g21 = g_y2p + (size_t)p1 * Y2N;
        #pragma unroll
        for (int t = 0; t < L2; t++) {
            g20[o * L2 + t] = acc0[t];
            g21[o * L2 + t] = acc1[t];
            bnS += acc0[t].x + acc0[t].y + acc1[t].x + acc1[t].y;
            bnQ = fmaf(acc0[t].x, acc0[t].x, fmaf(acc0[t].y, acc0[t].y, bnQ));
            bnQ = fmaf(acc1[t].x, acc1[t].x, fmaf(acc1[t].y, acc1[t].y, bnQ));
        }
        __syncwarp();
    }
    atomicAdd(&g_stats[32 + o], bnS);
    atomicAdd(&g_stats[64 + o], bnQ);
}

// ---- K3: BN2+tanh, heads, reparam, decoder — loop-invariants in registers --
#define K3_WPB 8
__global__ void __launch_bounds__(K3_WPB * 32) k3_kernel(
    const float* __restrict__ eps,
    const float* __restrict__ mu_w, const float* __restrict__ mu_b,
    const float* __restrict__ lv_w, const float* __restrict__ lv_b,
    const float* __restrict__ de_w1, const float* __restrict__ de_b1,
    const float* __restrict__ de_w2, const float* __restrict__ de_b2,
    const float* __restrict__ bn2_g, const float* __restrict__ bn2_b,
    float* __restrict__ out, int bsz)
{
    __shared__ float  s_dw1[DEH * 2], s_db1[DEH];
    __shared__ float2 s_dw2d[DEOUT * DEH];
    __shared__ float2 s_db2d[DEOUT];
    __shared__ float  s_sc[EN2], s_sh[EN2];
    __shared__ float2 s_d[K3_WPB][12];

    const int tid = threadIdx.x;
    for (int i = tid; i < DEH * 2; i += blockDim.x) s_dw1[i] = de_w1[i];
    if (tid < DEH) s_db1[tid] = de_b1[tid];
    for (int i = tid; i < DEOUT * DEH; i += blockDim.x) s_dw2d[i] = fdup(de_w2[i]);
    if (tid < DEOUT) s_db2d[tid] = fdup(de_b2[tid]);
    if (tid < EN2) {
        float inv = 1.0f / ((float)bsz * (float)L2);
        float m = g_stats[32 + tid] * inv;
        float v = g_stats[64 + tid] * inv - m * m;
        float r = rsqrtf(v + 1e-5f);
        float sc = bn2_g[tid] * r;
        s_sc[tid] = sc;
        s_sh[tid] = bn2_b[tid] - m * sc;
    }
    __syncthreads();

    const int lane = tid & 31;
    const int w    = tid >> 5;

    float2 rmu0[5], rmu1[5], rlv0[5], rlv1[5], rsc[5], rsh[5];
    #pragma unroll
    for (int j = 0; j < 5; j++) {
        int i = lane + 32 * j;
        int c = i / L2;
        rmu0[j] = fdup(mu_w[i]);       rmu1[j] = fdup(mu_w[Y2N + i]);
        rlv0[j] = fdup(lv_w[i]);       rlv1[j] = fdup(lv_w[Y2N + i]);
        rsc[j]  = fdup(s_sc[c]);       rsh[j]  = fdup(s_sh[c]);
    }
    const float mub0 = mu_b[0], mub1 = mu_b[1];
    const float lvb0 = lv_b[0], lvb1 = lv_b[1];

    const int wpb  = blockDim.x >> 5;
    const int gw   = blockIdx.x * wpb + w;
    const int nw   = gridDim.x * wpb;
    const int npairs = bsz >> 1;

    float* outO = out;
    float* outM = out + (size_t)bsz * DEOUT;
    float* outV = out + (size_t)bsz * (DEOUT + 2);

    for (int p = gw; p < npairs; p += nw) {
        const int b0 = 2 * p;
        const float2* gy = g_y2p + (size_t)p * Y2N;
        float2 pm0 = make_float2(0.f, 0.f), pm1 = pm0, pl0 = pm0, pl1 = pm0;
        #pragma unroll
        for (int j = 0; j < 5; j++) {
            float2 v = ftanha2(f2fma(gy[lane + 32 * j], rsc[j], rsh[j]));
            pm0 = f2fma(v, rmu0[j], pm0);
            pm1 = f2fma(v, rmu1[j], pm1);
            pl0 = f2fma(v, rlv0[j], pl0);
            pl1 = f2fma(v, rlv1[j], pl1);
        }
        #pragma unroll
        for (int off = 16; off > 0; off >>= 1) {
            pm0.x += __shfl_xor_sync(0xffffffffu, pm0.x, off);
            pm0.y += __shfl_xor_sync(0xffffffffu, pm0.y, off);
            pm1.x += __shfl_xor_sync(0xffffffffu, pm1.x, off);
            pm1.y += __shfl_xor_sync(0xffffffffu, pm1.y, off);
            pl0.x += __shfl_xor_sync(0xffffffffu, pl0.x, off);
            pl0.y += __shfl_xor_sync(0xffffffffu, pl0.y, off);
            pl1.x += __shfl_xor_sync(0xffffffffu, pl1.x, off);
            pl1.y += __shfl_xor_sync(0xffffffffu, pl1.y, off);
        }
        float2 mu0 = f2add(pm0, fdup(mub0));
        float2 mu1 = f2add(pm1, fdup(mub1));
        float2 lv0 = f2add(pl0, fdup(lvb0));
        float2 lv1 = f2add(pl1, fdup(lvb1));
        const float4 ev = *(const float4*)(eps + (size_t)b0 * 2);
        float2 z0 = make_float2(fmaf(ev.x, __expf(0.5f * lv0.x), mu0.x),
                                fmaf(ev.z, __expf(0.5f * lv0.y), mu0.y));
        float2 z1 = make_float2(fmaf(ev.y, __expf(0.5f * lv1.x), mu1.x),
                                fmaf(ev.w, __expf(0.5f * lv1.y), mu1.y));

        if (lane < DEH) {
            float2 a = f2fma(z0, fdup(s_dw1[lane * 2]),
                       f2fma(z1, fdup(s_dw1[lane * 2 + 1]), fdup(s_db1[lane])));
            s_d[w][lane] = ftanha2(a);
        }
        __syncwarp();
        float2 dreg[DEH];
        #pragma unroll
        for (int j = 0; j < DEH; j++) dreg[j] = s_d[w][j];

        float* oo0 = outO + (size_t)b0 * DEOUT;
        float* oo1 = oo0 + DEOUT;
        for (int k = lane; k < DEOUT; k += 32) {
            float2 a = s_db2d[k];
            #pragma unroll
            for (int j = 0; j < DEH; j++)
                a = f2fma(dreg[j], s_dw2d[k * DEH + j], a);
            a = ftanh2(a);   // precise: final output
            oo0[k] = a.x;
            oo1[k] = a.y;
        }
        if (lane == 0) {
            *(float2*)(outM + (size_t)b0 * 2)       = make_float2(mu0.x, mu1.x);
            *(float2*)(outM + (size_t)(b0 + 1) * 2) = make_float2(mu0.y, mu1.y);
            *(float2*)(outV + (size_t)b0 * 2)       = make_float2(lv0.x, lv1.x);
            *(float2*)(outV + (size_t)(b0 + 1) * 2) = make_float2(lv0.y, lv1.y);
        }
        __syncwarp();
    }
}

extern "C" void kernel_launch(void* const* d_in, const int* in_sizes, int n_in,
                              void* d_out, int out_size)
{
    const float* raw    = (const float*)d_in[0];
    const float* eegf   = (const float*)d_in[1];
    const float* eps    = (const float*)d_in[2];
    const float* fg_w1  = (const float*)d_in[3];
    const float* fg_b1  = (const float*)d_in[4];
    const float* fg_w2  = (const float*)d_in[5];
    const float* fg_b2  = (const float*)d_in[6];
    const float* enc_w1 = (const float*)d_in[7];
    const float* enc_b1 = (const float*)d_in[8];
    const float* bn1_g  = (const float*)d_in[9];
    const float* bn1_b  = (const float*)d_in[10];
    const float* enc_w2 = (const float*)d_in[11];
    const float* enc_b2 = (const float*)d_in[12];
    const float* bn2_g  = (const float*)d_in[13];
    const float* bn2_b  = (const float*)d_in[14];
    const float* mu_w   = (const float*)d_in[15];
    const float* mu_b   = (const float*)d_in[16];
    const float* lv_w   = (const float*)d_in[17];
    const float* lv_b   = (const float*)d_in[18];
    const float* de_w1  = (const float*)d_in[19];
    const float* de_b1  = (const float*)d_in[20];
    const float* de_w2  = (const float*)d_in[21];
    const float* de_b2  = (const float*)d_in[22];

    int bsz = in_sizes[0] / (CH * LRAW);

    size_t smemA = (size_t)K1A_SMEMF * sizeof(float);
    cudaFuncSetAttribute((const void*)k1a_kernel,
                         cudaFuncAttributeMaxDynamicSharedMemorySize, (int)smemA);
    k1a_kernel<<<296, K1A_WARPS * 32, smemA>>>(eegf, fg_w1, fg_b1, fg_w2, fg_b2, bsz);

    size_t smemB = (size_t)K1B_SMEMF * sizeof(float);
    cudaFuncSetAttribute((const void*)k1b_kernel,
                         cudaFuncAttributeMaxDynamicSharedMemorySize, (int)smemB);
    k1b_kernel<<<444, K1B_WARPS * 32, smemB>>>(raw, enc_w1, enc_b1, bsz);

    size_t smem2 = (size_t)K2_SMEMF * sizeof(float);
    cudaFuncSetAttribute((const void*)k2_kernel,
                         cudaFuncAttributeMaxDynamicSharedMemorySize, (int)smem2);
    k2_kernel<<<444, K2_WARPS * 32, smem2>>>(enc_w2, enc_b2, bn1_g, bn1_b, bsz);

    k3_kernel<<<444, K3_WPB * 32>>>(eps, mu_w, mu_b, lv_w, lv_b,
                                    de_w1, de_b1, de_w2, de_b2,
                                    bn2_g, bn2_b, (float*)d_out, bsz);
}